// round 14
// baseline (speedup 1.0000x reference)
#include <cuda_runtime.h>
#include <cuda_fp16.h>
#include <cstdint>

#define EPSF 1e-6f

// Problem constants (B=4, T=4096, D=1024, H=4, d=64)
#define BB    4
#define TT    4096
#define DDIM  1024
#define HH    4
#define HD    64
#define NTOK  (BB*TT)        // 16384
#define QKVW  768
#define CHUNK 64
#define NCH   (TT/CHUNK)     // 64
#define NBH   (BB*HH)        // 16
#define YSZ   (16777216)     // NTOK*DDIM
#define KVSZ  (65536)        // NBH*64*64

// ---------------- scratch (device globals; no allocations allowed) ----------
__device__ __align__(128) __half g_qkv[(size_t)NTOK * QKVW];         // 24 MB (fp16)
__device__ __align__(128) float g_Sc [(size_t)NBH * NCH * 4096];     // 16 MB
__device__ __align__(128) __half g_S0[(size_t)NBH * NCH * 4096];     // 8 MB (fp16)
__device__ __align__(128) float g_kc [(size_t)NBH * NCH * 64];
__device__ __align__(128) float g_kc0[(size_t)NBH * NCH * 64];
// fp16 operand copies
__device__ __align__(128) __half g_xh[(size_t)NTOK * DDIM];          // 32 MB
__device__ __align__(128) __half g_Wh[(size_t)QKVW * DDIM];          // 1.5 MB
__device__ __align__(128) __half g_Woh[(size_t)DDIM * 256];
__device__ __align__(128) __half g_yh[(size_t)NTOK * 256];           // 8 MB

// ======================= PTX helpers (arch-neutral) =========================
__device__ __forceinline__ uint32_t smem_to_u32(const void* p) {
    uint32_t a;
    asm("{ .reg .u64 t; cvta.to.shared.u64 t, %1; cvt.u32.u64 %0, t; }"
        : "=r"(a) : "l"(p));
    return a;
}
#define LDMX4(R, addr) \
    asm volatile("ldmatrix.sync.aligned.m8n8.x4.shared.b16 {%0,%1,%2,%3}, [%4];" \
        : "=r"((R)[0]), "=r"((R)[1]), "=r"((R)[2]), "=r"((R)[3]) : "r"(addr))
#define LDMX4T(R, addr) \
    asm volatile("ldmatrix.sync.aligned.m8n8.x4.trans.shared.b16 {%0,%1,%2,%3}, [%4];" \
        : "=r"((R)[0]), "=r"((R)[1]), "=r"((R)[2]), "=r"((R)[3]) : "r"(addr))
#define MMA_FP16(D, A, B) \
    asm volatile("mma.sync.aligned.m16n8k16.row.col.f32.f16.f16.f32 " \
        "{%0,%1,%2,%3},{%4,%5,%6,%7},{%8,%9},{%0,%1,%2,%3};" \
        : "+f"((D)[0]), "+f"((D)[1]), "+f"((D)[2]), "+f"((D)[3]) \
        : "r"((A)[0]), "r"((A)[1]), "r"((A)[2]), "r"((A)[3]), \
          "r"((B)[0]), "r"((B)[1]))
__device__ __forceinline__ void cpa16(uint32_t dst, const void* src) {
    asm volatile("cp.async.cg.shared.global [%0], [%1], 16;"
                 :: "r"(dst), "l"(src) : "memory");
}
#define CPA_COMMIT() asm volatile("cp.async.commit_group;" ::: "memory")
#define CPA_WAIT1()  asm volatile("cp.async.wait_group 1;"  ::: "memory")

__device__ __forceinline__ uint32_t pack_h(float a, float b) {
    __half2 t;
    t.x = __float2half_rn(a);
    t.y = __float2half_rn(b);
    return *(uint32_t*)&t;
}
// exact fp16 (hi, lo) split of a float pair
__device__ __forceinline__ void split2h(float a, float b, uint32_t& h, uint32_t& l) {
    float ha = __half2float(__float2half_rn(a));
    float hb = __half2float(__float2half_rn(b));
    h = pack_h(a, b);
    l = pack_h(a - ha, b - hb);
}
// exact fp16 (hi, lo) split of a float4
__device__ __forceinline__ void split4h(float4 v, uint2& h, uint2& l) {
    split2h(v.x, v.y, h.x, l.x);
    split2h(v.z, v.w, h.y, l.y);
}
// 4 halves (uint2) -> float4
__device__ __forceinline__ float4 h4f(uint2 u) {
    __half2 a = *(__half2*)&u.x;
    __half2 b = *(__half2*)&u.y;
    return make_float4(__half2float(a.x), __half2float(a.y),
                       __half2float(b.x), __half2float(b.y));
}

// ---------------- fp32 -> fp16 round (x) ------------------------------------
__global__ void __launch_bounds__(256) convert_round(
    const float4* __restrict__ src, uint2* __restrict__ dh, int n4)
{
    int i = blockIdx.x * 256 + threadIdx.x;
    if (i < n4) {
        float4 v = src[i];
        dh[i] = make_uint2(pack_h(v.x, v.y), pack_h(v.z, v.w));
    }
}
// ---------------- all 4 weight matrices -> fp16 in one launch ---------------
__global__ void __launch_bounds__(256) convert_weights(
    const float4* __restrict__ Wq, const float4* __restrict__ Wk,
    const float4* __restrict__ Wv, const float4* __restrict__ Wo,
    uint2* __restrict__ Wh, uint2* __restrict__ Woh)
{
    const int i = blockIdx.x * 256 + threadIdx.x;   // 0..65535
    const int m = blockIdx.y;
    const float4* src = (m == 0) ? Wq : (m == 1) ? Wk : (m == 2) ? Wv : Wo;
    float4 v = src[i];
    uint2 r = make_uint2(pack_h(v.x, v.y), pack_h(v.z, v.w));
    if (m < 3) Wh[(size_t)m * 65536 + i] = r;
    else       Woh[i] = r;
}

// ====== fp16 HMMA GEMM: C = Ah @ Bh^T (BK=32, 3-stage) ======================
#define LDS_A   40
#define TILE_B  (128 * LDS_A * 2)
#define NSTAGE  3
#define GEMM_SMEM (NSTAGE * 2 * TILE_B)   // 61440

template <typename OutT>
__global__ void __launch_bounds__(256, 2) hmma_gemm_fp16(
    const __half* __restrict__ Ah, int lda,
    const __half* __restrict__ Bh, int ldb,
    OutT* __restrict__ C, int ldc, int K)
{
    extern __shared__ __align__(128) char smem[];
    const uint32_t sbase = smem_to_u32(smem);
    const int tid = threadIdx.x;
    const int w = tid >> 5, lane = tid & 31;
    const int m0 = blockIdx.y * 128;
    const int n0 = blockIdx.x * 128;

    const int row0 = tid >> 2, c16 = tid & 3;
    const int row1 = (tid + 256) >> 2;
    const uint32_t d0 = (uint32_t)row0 * (LDS_A * 2) + c16 * 16;
    const uint32_t d1 = (uint32_t)row1 * (LDS_A * 2) + c16 * 16;
    const size_t aoff0 = (size_t)(m0 + row0) * lda + c16 * 8;
    const size_t aoff1 = (size_t)(m0 + row1) * lda + c16 * 8;
    const size_t boff0 = (size_t)(n0 + row0) * ldb + c16 * 8;
    const size_t boff1 = (size_t)(n0 + row1) * ldb + c16 * 8;

#define ISSUE_STAGE(sb, koff) do { \
        cpa16((sb) + d0, Ah + aoff0 + (koff)); \
        cpa16((sb) + d1, Ah + aoff1 + (koff)); \
        cpa16((sb) + TILE_B + d0, Bh + boff0 + (koff)); \
        cpa16((sb) + TILE_B + d1, Bh + boff1 + (koff)); \
    } while (0)

    float acc[4][4][4];
#pragma unroll
    for (int mt = 0; mt < 4; mt++)
#pragma unroll
        for (int nt = 0; nt < 4; nt++)
#pragma unroll
            for (int r = 0; r < 4; r++) acc[mt][nt][r] = 0.f;

    const int wm = w >> 2, wn = w & 3;
    const int aRow = wm * 64 + (lane & 15);
    const int aCol = (lane >> 4) * 8;
    const int bRow = wn * 32 + (lane & 7) + ((lane >> 4) << 3);
    const int bCol = (lane & 8);

    const int NC = K / 32;

    ISSUE_STAGE(sbase, 0);
    CPA_COMMIT();
    ISSUE_STAGE(sbase + 2 * TILE_B, 32);
    CPA_COMMIT();

    int s = 0;
    for (int c = 0; c < NC; c++) {
        CPA_WAIT1();
        __syncthreads();
        if (c + 2 < NC) {
            int s2 = s + 2; if (s2 >= NSTAGE) s2 -= NSTAGE;
            ISSUE_STAGE(sbase + s2 * (2 * TILE_B), (c + 2) * 32);
        }
        CPA_COMMIT();

        const uint32_t st = sbase + s * (2 * TILE_B);
        const uint32_t sA = st, sB = st + TILE_B;
#pragma unroll
        for (int ks = 0; ks < 2; ks++) {
            const int kb = ks * 16;
            uint32_t bAddr = ((uint32_t)bRow * LDS_A + kb + bCol) * 2;
            uint32_t aAddr = ((uint32_t)aRow * LDS_A + kb + aCol) * 2;
            uint32_t bf[2][4], af[4][4];
#pragma unroll
            for (int nt2 = 0; nt2 < 2; nt2++)
                LDMX4(bf[nt2], sB + bAddr + nt2 * (16 * LDS_A * 2));
#pragma unroll
            for (int mt = 0; mt < 4; mt++)
                LDMX4(af[mt], sA + aAddr + mt * (16 * LDS_A * 2));
#pragma unroll
            for (int mt = 0; mt < 4; mt++)
#pragma unroll
                for (int nt = 0; nt < 4; nt++)
                    MMA_FP16(acc[mt][nt], af[mt], &bf[nt >> 1][(nt & 1) * 2]);
        }
        if (++s == NSTAGE) s = 0;
    }
#undef ISSUE_STAGE

    const int gr = lane >> 2, gc = (lane & 3) * 2;
#pragma unroll
    for (int mt = 0; mt < 4; mt++) {
#pragma unroll
        for (int nt = 0; nt < 4; nt++) {
            OutT* dst = C + (size_t)(m0 + wm * 64 + mt * 16 + gr) * ldc
                          + n0 + wn * 32 + nt * 8 + gc;
            if (sizeof(OutT) == 2) {
                *(uint32_t*)dst = pack_h(acc[mt][nt][0], acc[mt][nt][1]);
                *(uint32_t*)(dst + (size_t)8 * ldc) =
                    pack_h(acc[mt][nt][2], acc[mt][nt][3]);
            } else {
                *(float2*)dst = make_float2(acc[mt][nt][0], acc[mt][nt][1]);
                *(float2*)(dst + (size_t)8 * ldc) =
                    make_float2(acc[mt][nt][2], acc[mt][nt][3]);
            }
        }
    }
}

// ---------------- fused pos_unit helper (per 4 elems, 16-lane row groups) ---
__device__ __forceinline__ float4 posunit4(float4 v) {
    float4 p;
    p.x = v.x > 0.f ? v.x + 1.f : __expf(v.x);
    p.y = v.y > 0.f ? v.y + 1.f : __expf(v.y);
    p.z = v.z > 0.f ? v.z + 1.f : __expf(v.z);
    p.w = v.w > 0.f ? v.w + 1.f : __expf(v.w);
    float s = p.x * p.x + p.y * p.y + p.z * p.z + p.w * p.w;
    s += __shfl_xor_sync(0xffffffffu, s, 8);
    s += __shfl_xor_sync(0xffffffffu, s, 4);
    s += __shfl_xor_sync(0xffffffffu, s, 2);
    s += __shfl_xor_sync(0xffffffffu, s, 1);
    float inv = 1.0f / (sqrtf(s) + EPSF);
    p.x *= inv; p.y *= inv; p.z *= inv; p.w *= inv;
    return p;
}

// ====== per-chunk sums via HMMA with ldmatrix.trans (row-major staging) =====
// Sc[j][dd] = sum_t v[t][j]*k[t][dd]; A = V^T (trans from Vr[t][j]),
// B = K^T (trans from Krh/Krl[t][dd], exact hi/lo split of posunit'd k).
#define CST 72
#define CBUF (64 * CST)
__global__ void __launch_bounds__(256) chunksum_kernel(
    const __half* __restrict__ qkv, float* __restrict__ Sc, float* __restrict__ kcs)
{
    __shared__ __align__(128) __half Krh[CBUF];
    __shared__ __align__(128) __half Krl[CBUF];
    __shared__ __align__(128) __half Vr [CBUF];

    const int tid = threadIdx.x;
    const int w = tid >> 5, lane = tid & 31;
    const int c = blockIdx.x, bh = blockIdx.y;
    const int b = bh >> 2, h = bh & 3;
    const int nbase = b * TT + c * CHUNK;
    const int rowb = tid >> 4;
    const int dq = (tid & 15) * 4;

    // stage: k -> posunit -> exact split, row-major; v -> raw fp16 copy
#pragma unroll
    for (int rep = 0; rep < 4; rep++) {
        int t = rowb + rep * 16;
        const __half* src = qkv + (size_t)(nbase + t) * QKVW + h * 64 + dq;
        float4 k4 = posunit4(h4f(*(const uint2*)(src + 256)));
        uint2 hh, ll;
        split4h(k4, hh, ll);
        *(uint2*)&Krh[t * CST + dq] = hh;
        *(uint2*)&Krl[t * CST + dq] = ll;
        *(uint2*)&Vr[t * CST + dq] = *(const uint2*)(src + 512);
    }
    __syncthreads();

    // kcs: column sums of exact k = hi + lo
    if (tid < 64) {
        float s = 0.f;
#pragma unroll 8
        for (int t = 0; t < 64; t++)
            s += __half2float(Krh[t * CST + tid]) + __half2float(Krl[t * CST + tid]);
        kcs[((size_t)bh * NCH + c) * 64 + tid] = s;
    }

    // MMA: warp grid 4x2; warp tile m16 (j) x n32 (dd)
    const int wm = w >> 1, wn = w & 1;
    const uint32_t sV = smem_to_u32(Vr);
    const uint32_t sKh = smem_to_u32(Krh), sKl = smem_to_u32(Krl);
    // A-trans lane address components (rows = t, col = j)
    const uint32_t aT = (lane & 7) + ((lane >> 4) << 3);   // t offset within step
    const uint32_t aJ = wm * 16 + (lane & 8);
    // B-trans lane address components (rows = t, col = dd)
    const uint32_t bT = (lane & 7) + (lane & 8);
    const uint32_t bD = wn * 32 + ((lane >> 4) << 3);

    float acc[4][4];
#pragma unroll
    for (int nb = 0; nb < 4; nb++)
#pragma unroll
        for (int r = 0; r < 4; r++) acc[nb][r] = 0.f;

#pragma unroll
    for (int ks = 0; ks < 4; ks++) {
        const uint32_t t0 = ks * 16;
        uint32_t af[4], bh0[4], bh1[4], bl0[4], bl1[4];
        LDMX4T(af, sV + ((t0 + aT) * CST + aJ) * 2);
        const uint32_t bo = ((t0 + bT) * CST + bD) * 2;
        LDMX4T(bh0, sKh + bo);
        LDMX4T(bh1, sKh + bo + 16 * 2);      // dd + 16
        LDMX4T(bl0, sKl + bo);
        LDMX4T(bl1, sKl + bo + 16 * 2);
        MMA_FP16(acc[0], af, &bh0[0]);
        MMA_FP16(acc[1], af, &bh0[2]);
        MMA_FP16(acc[2], af, &bh1[0]);
        MMA_FP16(acc[3], af, &bh1[2]);
        MMA_FP16(acc[0], af, &bl0[0]);
        MMA_FP16(acc[1], af, &bl0[2]);
        MMA_FP16(acc[2], af, &bl1[0]);
        MMA_FP16(acc[3], af, &bl1[2]);
    }

    const int gr = lane >> 2, gc = (lane & 3) * 2;
    size_t base = ((size_t)bh * NCH + c) * 4096;
#pragma unroll
    for (int nb = 0; nb < 4; nb++) {
        int j0 = wm * 16 + gr;
        int d0 = wn * 32 + nb * 8 + gc;
        *(float2*)(Sc + base + (size_t)j0 * 64 + d0) =
            make_float2(acc[nb][0], acc[nb][1]);
        *(float2*)(Sc + base + (size_t)(j0 + 8) * 64 + d0) =
            make_float2(acc[nb][2], acc[nb][3]);
    }
}

// ---------------- exclusive prefix over chunks; S0 written as fp16 ---------
__global__ void __launch_bounds__(256) prefix_kernel(
    const float* __restrict__ Sc, const float* __restrict__ kcs,
    __half* __restrict__ S0, float* __restrict__ kc0,
    float* __restrict__ dout, int out_size)
{
    const int tid = threadIdx.x;
    const int bh = blockIdx.y;
    const int e = blockIdx.x * 256 + tid;   // 0..4095
    float acc = 0.f;
    size_t idx = (size_t)bh * NCH * 4096 + e;
#pragma unroll 4
    for (int c = 0; c < NCH; c += 4) {
        float v0 = Sc[idx];
        float v1 = Sc[idx + 4096];
        float v2 = Sc[idx + 8192];
        float v3 = Sc[idx + 12288];
        S0[idx] = __float2half_rn(acc);          acc += v0;
        S0[idx + 4096] = __float2half_rn(acc);   acc += v1;
        S0[idx + 8192] = __float2half_rn(acc);   acc += v2;
        S0[idx + 12288] = __float2half_rn(acc);  acc += v3;
        idx += 4 * 4096;
    }
    int kvoff = YSZ + bh * 4096 + e;
    if (kvoff < out_size) dout[kvoff] = acc;    // kv_f [B,H,j,d] (fp32)
    if (blockIdx.x == 0 && tid < 64) {
        float a2 = 0.f;
        size_t kidx = (size_t)bh * NCH * 64 + tid;
#pragma unroll 4
        for (int c = 0; c < NCH; c += 4) {
            float v0 = kcs[kidx];
            float v1 = kcs[kidx + 64];
            float v2 = kcs[kidx + 128];
            float v3 = kcs[kidx + 192];
            kc0[kidx] = a2;        a2 += v0;
            kc0[kidx + 64] = a2;   a2 += v1;
            kc0[kidx + 128] = a2;  a2 += v2;
            kc0[kidx + 192] = a2;  a2 += v3;
            kidx += 256;
        }
        int kcoff = YSZ + KVSZ + bh * 64 + tid;
        if (kcoff < out_size) dout[kcoff] = a2; // kc_f [B,H,d]
    }
}

// =========== intra-chunk attention via split-fp16 HMMA (R13 form) ==========
#define IST 72
#define IBUF (64 * IST)
#define INTRA_SMEM (6 * IBUF * 2 + 128 * 4)

// one 64x64x64 MMA-accumulate: acc += A(sA) @ B(sB)^T, warp tile 16x32
__device__ __forceinline__ void mm64(
    uint32_t sA, uint32_t sB, int wm, int wn, int lane, float acc[4][4])
{
    const uint32_t aBase = sA +
        (((uint32_t)(wm * 16 + (lane & 15)) * IST + ((lane >> 4) * 8)) * 2);
    const uint32_t bBase = sB +
        (((uint32_t)(wn * 32 + (lane & 7) + ((lane >> 4) << 3)) * IST + (lane & 8)) * 2);
#pragma unroll
    for (int ks = 0; ks < 4; ks++) {
        const uint32_t ko = ks * 32;   // 16 halves
        uint32_t af[4], bf0[4], bf1[4];
        LDMX4(af, aBase + ko);
        LDMX4(bf0, bBase + ko);
        LDMX4(bf1, bBase + ko + 16 * IST * 2);
        MMA_FP16(acc[0], af, &bf0[0]);
        MMA_FP16(acc[1], af, &bf0[2]);
        MMA_FP16(acc[2], af, &bf1[0]);
        MMA_FP16(acc[3], af, &bf1[2]);
    }
}

__global__ void __launch_bounds__(256) intra_kernel(
    const __half* __restrict__ qkv, const __half* __restrict__ S0g,
    const float* __restrict__ kc0g,
    __half* __restrict__ yh)
{
    extern __shared__ __align__(128) char ism[];
    __half* bufs = (__half*)ism;
    __half* Qh  = bufs;             __half* Ql  = bufs + 1 * IBUF;
    __half* Ahb = bufs + 2 * IBUF;  __half* Alb = bufs + 3 * IBUF;  // K then A
    __half* Vth = bufs + 4 * IBUF;
    __half* S0h = bufs + 5 * IBUF;
    float* dens = (float*)(bufs + 6 * IBUF);
    float* kc0s = dens + 64;

    const uint32_t sQh = smem_to_u32(Qh),  sQl = smem_to_u32(Ql);
    const uint32_t sAh = smem_to_u32(Ahb), sAl = smem_to_u32(Alb);
    const uint32_t sVh = smem_to_u32(Vth);
    const uint32_t sSh = smem_to_u32(S0h);

    const int tid = threadIdx.x;
    const int w = tid >> 5, lane = tid & 31;
    const int c = blockIdx.x, bh = blockIdx.y;
    const int b = bh >> 2, h = bh & 3;
    const int nbase = b * TT + c * CHUNK;
    const int rowb = tid >> 4;
    const int dq = (tid & 15) * 4;
    const size_t s0base = ((size_t)bh * NCH + c) * 4096;

    // ---- load + posunit + split to fp16 smem ----
#pragma unroll
    for (int rep = 0; rep < 4; rep++) {
        int t = rowb + rep * 16;
        const __half* src = qkv + (size_t)(nbase + t) * QKVW + h * 64 + dq;
        float4 q4 = posunit4(h4f(*(const uint2*)(src)));
        float4 k4 = posunit4(h4f(*(const uint2*)(src + 256)));
        uint2 v2 = *(const uint2*)(src + 512);               // fp16-exact
        uint2 s2 = *(const uint2*)(S0g + s0base + (size_t)t * 64 + dq); // fp16
        uint2 hh, ll;
        split4h(q4, hh, ll);
        *(uint2*)&Qh[t * IST + dq] = hh;  *(uint2*)&Ql[t * IST + dq] = ll;
        split4h(k4, hh, ll);
        *(uint2*)&Ahb[t * IST + dq] = hh; *(uint2*)&Alb[t * IST + dq] = ll;
        *(uint2*)&S0h[t * IST + dq] = s2;
        // V transposed: Vt[j][t]
        __half2 va = *(__half2*)&v2.x;
        __half2 vb = *(__half2*)&v2.y;
        Vth[(dq + 0) * IST + t] = va.x;
        Vth[(dq + 1) * IST + t] = va.y;
        Vth[(dq + 2) * IST + t] = vb.x;
        Vth[(dq + 3) * IST + t] = vb.y;
    }
    if (tid < 64) {
        dens[tid] = EPSF;
        kc0s[tid] = kc0g[((size_t)bh * NCH + c) * 64 + tid];
    }
    __syncthreads();

    const int wm = w >> 1, wn = w & 1;      // 4x2 warp grid, tile 16x32
    const int gr = lane >> 2, gc = (lane & 3) * 2;
    const int r0 = wm * 16 + gr, r1 = r0 + 8;

    // ---- A = Q K^T (3 split terms) ----
    float a4[4][4];
#pragma unroll
    for (int nt = 0; nt < 4; nt++)
#pragma unroll
        for (int r = 0; r < 4; r++) a4[nt][r] = 0.f;
    mm64(sQh, sAh, wm, wn, lane, a4);
    mm64(sQh, sAl, wm, wn, lane, a4);
    mm64(sQl, sAh, wm, wn, lane, a4);
    __syncthreads();   // everyone done reading K before A overwrites it

    // ---- mask tril, row-sums, split-store A over K buffers ----
    float s0 = 0.f, s1 = 0.f;
#pragma unroll
    for (int nt = 0; nt < 4; nt++) {
        int c0 = wn * 32 + nt * 8 + gc;
        float m00 = (c0     <= r0) ? a4[nt][0] : 0.f;
        float m01 = (c0 + 1 <= r0) ? a4[nt][1] : 0.f;
        float m10 = (c0     <= r1) ? a4[nt][2] : 0.f;
        float m11 = (c0 + 1 <= r1) ? a4[nt][3] : 0.f;
        s0 += m00 + m01;
        s1 += m10 + m11;
        uint32_t hh, ll;
        split2h(m00, m01, hh, ll);
        *(uint32_t*)&Ahb[r0 * IST + c0] = hh;
        *(uint32_t*)&Alb[r0 * IST + c0] = ll;
        split2h(m10, m11, hh, ll);
        *(uint32_t*)&Ahb[r1 * IST + c0] = hh;
        *(uint32_t*)&Alb[r1 * IST + c0] = ll;
    }
    s0 += __shfl_xor_sync(0xffffffffu, s0, 1);
    s0 += __shfl_xor_sync(0xffffffffu, s0, 2);
    s1 += __shfl_xor_sync(0xffffffffu, s1, 1);
    s1 += __shfl_xor_sync(0xffffffffu, s1, 2);
    if ((lane & 3) == 0) {
        atomicAdd(&dens[r0], s0);
        atomicAdd(&dens[r1], s1);
    }
    // den += q . kc0 (exact q = Qh + Ql)
    if (tid < 64) {
        float qd = 0.f;
        for (int dd = 0; dd < 64; dd++)
            qd += (__half2float(Qh[tid * IST + dd]) +
                   __half2float(Ql[tid * IST + dd])) * kc0s[dd];
        atomicAdd(&dens[tid], qd);
    }
    __syncthreads();

    // ---- num = A V + Q S0 (2 + 2 terms; Vl = S0l = 0) ----
    float y4[4][4];
#pragma unroll
    for (int nt = 0; nt < 4; nt++)
#pragma unroll
        for (int r = 0; r < 4; r++) y4[nt][r] = 0.f;
    mm64(sAh, sVh, wm, wn, lane, y4);
    mm64(sAl, sVh, wm, wn, lane, y4);
    mm64(sQh, sSh, wm, wn, lane, y4);
    mm64(sQl, sSh, wm, wn, lane, y4);

    const float inv0 = 1.0f / dens[r0];
    const float inv1 = 1.0f / dens[r1];
#pragma unroll
    for (int nt = 0; nt < 4; nt++) {
        int c0 = wn * 32 + nt * 8 + gc;
        size_t off0 = (size_t)(nbase + r0) * 256 + h * 64 + c0;
        *(uint32_t*)&yh[off0] = pack_h(y4[nt][0] * inv0, y4[nt][1] * inv0);
        size_t off1 = (size_t)(nbase + r1) * 256 + h * 64 + c0;
        *(uint32_t*)&yh[off1] = pack_h(y4[nt][2] * inv1, y4[nt][3] * inv1);
    }
}

// ---------------------------------------------------------------------------
extern "C" void kernel_launch(void* const* d_in, const int* in_sizes, int n_in,
                              void* d_out, int out_size)
{
    const float* x  = (const float*)d_in[0];
    const float* Wq = (const float*)d_in[1];
    const float* Wk = (const float*)d_in[2];
    const float* Wv = (const float*)d_in[3];
    const float* Wo = (const float*)d_in[4];
    float* out = (float*)d_out;

    float *Sc, *kc, *kc0;
    __half *qkv, *S0, *xh, *Wh, *Woh, *yh;
    cudaGetSymbolAddress((void**)&qkv, g_qkv);
    cudaGetSymbolAddress((void**)&Sc,  g_Sc);
    cudaGetSymbolAddress((void**)&S0,  g_S0);
    cudaGetSymbolAddress((void**)&kc,  g_kc);
    cudaGetSymbolAddress((void**)&kc0, g_kc0);
    cudaGetSymbolAddress((void**)&xh,  g_xh);
    cudaGetSymbolAddress((void**)&Wh,  g_Wh);
    cudaGetSymbolAddress((void**)&Woh, g_Woh);
    cudaGetSymbolAddress((void**)&yh,  g_yh);

    cudaFuncSetAttribute(intra_kernel,
                         cudaFuncAttributeMaxDynamicSharedMemorySize, INTRA_SMEM);
    cudaFuncSetAttribute(hmma_gemm_fp16<__half>,
                         cudaFuncAttributeMaxDynamicSharedMemorySize, GEMM_SMEM);
    cudaFuncSetAttribute(hmma_gemm_fp16<float>,
                         cudaFuncAttributeMaxDynamicSharedMemorySize, GEMM_SMEM);

    // operand preparation: x -> fp16 (rounded); weights -> fp16
    convert_round<<<(NTOK * DDIM / 4 + 255) / 256, 256>>>(
        (const float4*)x, (uint2*)xh, NTOK * DDIM / 4);
    convert_weights<<<dim3(256, 4), 256>>>(
        (const float4*)Wq, (const float4*)Wk, (const float4*)Wv,
        (const float4*)Wo, (uint2*)Wh, (uint2*)Woh);

    // QKV projection: qkv[t][0:768] = xh @ [Wq;Wk;Wv]^T  (fp16 output)
    hmma_gemm_fp16<__half><<<dim3(6, NTOK / 128), 256, GEMM_SMEM>>>(
        xh, DDIM, Wh, DDIM, qkv, QKVW, DDIM);

    // chunked linear-attention scan (posunit fused into consumers)
    chunksum_kernel<<<dim3(NCH, NBH), 256>>>(qkv, Sc, kc);
    prefix_kernel<<<dim3(16, NBH), 256>>>(Sc, kc, S0, kc0, out, out_size);
    intra_kernel<<<dim3(NCH, NBH), 256, INTRA_SMEM>>>(qkv, S0, kc0, yh);

    // output projection: out = yh @ Wo^T (fp32 output)
    hmma_gemm_fp16<float><<<dim3(8, NTOK / 128), 256, GEMM_SMEM>>>(
        yh, 256, Woh, 256, out, DDIM, 256);
}

// round 15
// speedup vs baseline: 1.4158x; 1.4158x over previous
#include <cuda_runtime.h>
#include <cuda_fp16.h>
#include <cstdint>

#define EPSF 1e-6f

// Problem constants (B=4, T=4096, D=1024, H=4, d=64)
#define BB    4
#define TT    4096
#define DDIM  1024
#define HH    4
#define HD    64
#define NTOK  (BB*TT)        // 16384
#define QKVW  768
#define CHUNK 64
#define NCH   (TT/CHUNK)     // 64
#define NBH   (BB*HH)        // 16
#define YSZ   (16777216)     // NTOK*DDIM
#define KVSZ  (65536)        // NBH*64*64

// ---------------- scratch (device globals; no allocations allowed) ----------
__device__ __align__(128) __half g_qkv[(size_t)NTOK * QKVW];         // 24 MB (fp16)
__device__ __align__(128) float g_Sc [(size_t)NBH * NCH * 4096];     // 16 MB
__device__ __align__(128) __half g_S0[(size_t)NBH * NCH * 4096];     // 8 MB (fp16)
__device__ __align__(128) float g_kc [(size_t)NBH * NCH * 64];
__device__ __align__(128) float g_kc0[(size_t)NBH * NCH * 64];
// fp16 operand copies
__device__ __align__(128) __half g_xh[(size_t)NTOK * DDIM];          // 32 MB
__device__ __align__(128) __half g_Wh[(size_t)QKVW * DDIM];          // 1.5 MB
__device__ __align__(128) __half g_Woh[(size_t)DDIM * 256];
__device__ __align__(128) __half g_yh[(size_t)NTOK * 256];           // 8 MB

// ======================= PTX helpers (arch-neutral) =========================
__device__ __forceinline__ uint32_t smem_to_u32(const void* p) {
    uint32_t a;
    asm("{ .reg .u64 t; cvta.to.shared.u64 t, %1; cvt.u32.u64 %0, t; }"
        : "=r"(a) : "l"(p));
    return a;
}
#define LDMX4(R, addr) \
    asm volatile("ldmatrix.sync.aligned.m8n8.x4.shared.b16 {%0,%1,%2,%3}, [%4];" \
        : "=r"((R)[0]), "=r"((R)[1]), "=r"((R)[2]), "=r"((R)[3]) : "r"(addr))
#define MMA_FP16(D, A, B) \
    asm volatile("mma.sync.aligned.m16n8k16.row.col.f32.f16.f16.f32 " \
        "{%0,%1,%2,%3},{%4,%5,%6,%7},{%8,%9},{%0,%1,%2,%3};" \
        : "+f"((D)[0]), "+f"((D)[1]), "+f"((D)[2]), "+f"((D)[3]) \
        : "r"((A)[0]), "r"((A)[1]), "r"((A)[2]), "r"((A)[3]), \
          "r"((B)[0]), "r"((B)[1]))
__device__ __forceinline__ void cpa16(uint32_t dst, const void* src) {
    asm volatile("cp.async.cg.shared.global [%0], [%1], 16;"
                 :: "r"(dst), "l"(src) : "memory");
}
#define CPA_COMMIT() asm volatile("cp.async.commit_group;" ::: "memory")
#define CPA_WAIT1()  asm volatile("cp.async.wait_group 1;"  ::: "memory")

__device__ __forceinline__ uint32_t pack_h(float a, float b) {
    __half2 t;
    t.x = __float2half_rn(a);
    t.y = __float2half_rn(b);
    return *(uint32_t*)&t;
}
// exact fp16 (hi, lo) split of a float pair
__device__ __forceinline__ void split2h(float a, float b, uint32_t& h, uint32_t& l) {
    float ha = __half2float(__float2half_rn(a));
    float hb = __half2float(__float2half_rn(b));
    h = pack_h(a, b);
    l = pack_h(a - ha, b - hb);
}
// exact fp16 (hi, lo) split of a float4
__device__ __forceinline__ void split4h(float4 v, uint2& h, uint2& l) {
    split2h(v.x, v.y, h.x, l.x);
    split2h(v.z, v.w, h.y, l.y);
}
// 4 halves (uint2) -> float4
__device__ __forceinline__ float4 h4f(uint2 u) {
    __half2 a = *(__half2*)&u.x;
    __half2 b = *(__half2*)&u.y;
    return make_float4(__half2float(a.x), __half2float(a.y),
                       __half2float(b.x), __half2float(b.y));
}

// ---------------- fp32 -> fp16 round (x) ------------------------------------
__global__ void __launch_bounds__(256) convert_round(
    const float4* __restrict__ src, uint2* __restrict__ dh, int n4)
{
    int i = blockIdx.x * 256 + threadIdx.x;
    if (i < n4) {
        float4 v = src[i];
        dh[i] = make_uint2(pack_h(v.x, v.y), pack_h(v.z, v.w));
    }
}
// ---------------- all 4 weight matrices -> fp16 in one launch ---------------
__global__ void __launch_bounds__(256) convert_weights(
    const float4* __restrict__ Wq, const float4* __restrict__ Wk,
    const float4* __restrict__ Wv, const float4* __restrict__ Wo,
    uint2* __restrict__ Wh, uint2* __restrict__ Woh)
{
    const int i = blockIdx.x * 256 + threadIdx.x;   // 0..65535
    const int m = blockIdx.y;
    const float4* src = (m == 0) ? Wq : (m == 1) ? Wk : (m == 2) ? Wv : Wo;
    float4 v = src[i];
    uint2 r = make_uint2(pack_h(v.x, v.y), pack_h(v.z, v.w));
    if (m < 3) Wh[(size_t)m * 65536 + i] = r;
    else       Woh[i] = r;
}

// ====== fp16 HMMA GEMM: C = Ah @ Bh^T (BK=32, 3-stage) ======================
#define LDS_A   40
#define TILE_B  (128 * LDS_A * 2)
#define NSTAGE  3
#define GEMM_SMEM (NSTAGE * 2 * TILE_B)   // 61440

template <typename OutT>
__global__ void __launch_bounds__(256, 2) hmma_gemm_fp16(
    const __half* __restrict__ Ah, int lda,
    const __half* __restrict__ Bh, int ldb,
    OutT* __restrict__ C, int ldc, int K)
{
    extern __shared__ __align__(128) char smem[];
    const uint32_t sbase = smem_to_u32(smem);
    const int tid = threadIdx.x;
    const int w = tid >> 5, lane = tid & 31;
    const int m0 = blockIdx.y * 128;
    const int n0 = blockIdx.x * 128;

    const int row0 = tid >> 2, c16 = tid & 3;
    const int row1 = (tid + 256) >> 2;
    const uint32_t d0 = (uint32_t)row0 * (LDS_A * 2) + c16 * 16;
    const uint32_t d1 = (uint32_t)row1 * (LDS_A * 2) + c16 * 16;
    const size_t aoff0 = (size_t)(m0 + row0) * lda + c16 * 8;
    const size_t aoff1 = (size_t)(m0 + row1) * lda + c16 * 8;
    const size_t boff0 = (size_t)(n0 + row0) * ldb + c16 * 8;
    const size_t boff1 = (size_t)(n0 + row1) * ldb + c16 * 8;

#define ISSUE_STAGE(sb, koff) do { \
        cpa16((sb) + d0, Ah + aoff0 + (koff)); \
        cpa16((sb) + d1, Ah + aoff1 + (koff)); \
        cpa16((sb) + TILE_B + d0, Bh + boff0 + (koff)); \
        cpa16((sb) + TILE_B + d1, Bh + boff1 + (koff)); \
    } while (0)

    float acc[4][4][4];
#pragma unroll
    for (int mt = 0; mt < 4; mt++)
#pragma unroll
        for (int nt = 0; nt < 4; nt++)
#pragma unroll
            for (int r = 0; r < 4; r++) acc[mt][nt][r] = 0.f;

    const int wm = w >> 2, wn = w & 3;
    const int aRow = wm * 64 + (lane & 15);
    const int aCol = (lane >> 4) * 8;
    const int bRow = wn * 32 + (lane & 7) + ((lane >> 4) << 3);
    const int bCol = (lane & 8);

    const int NC = K / 32;

    ISSUE_STAGE(sbase, 0);
    CPA_COMMIT();
    ISSUE_STAGE(sbase + 2 * TILE_B, 32);
    CPA_COMMIT();

    int s = 0;
    for (int c = 0; c < NC; c++) {
        CPA_WAIT1();
        __syncthreads();
        if (c + 2 < NC) {
            int s2 = s + 2; if (s2 >= NSTAGE) s2 -= NSTAGE;
            ISSUE_STAGE(sbase + s2 * (2 * TILE_B), (c + 2) * 32);
        }
        CPA_COMMIT();

        const uint32_t st = sbase + s * (2 * TILE_B);
        const uint32_t sA = st, sB = st + TILE_B;
#pragma unroll
        for (int ks = 0; ks < 2; ks++) {
            const int kb = ks * 16;
            uint32_t bAddr = ((uint32_t)bRow * LDS_A + kb + bCol) * 2;
            uint32_t aAddr = ((uint32_t)aRow * LDS_A + kb + aCol) * 2;
            uint32_t bf[2][4], af[4][4];
#pragma unroll
            for (int nt2 = 0; nt2 < 2; nt2++)
                LDMX4(bf[nt2], sB + bAddr + nt2 * (16 * LDS_A * 2));
#pragma unroll
            for (int mt = 0; mt < 4; mt++)
                LDMX4(af[mt], sA + aAddr + mt * (16 * LDS_A * 2));
#pragma unroll
            for (int mt = 0; mt < 4; mt++)
#pragma unroll
                for (int nt = 0; nt < 4; nt++)
                    MMA_FP16(acc[mt][nt], af[mt], &bf[nt >> 1][(nt & 1) * 2]);
        }
        if (++s == NSTAGE) s = 0;
    }
#undef ISSUE_STAGE

    const int gr = lane >> 2, gc = (lane & 3) * 2;
#pragma unroll
    for (int mt = 0; mt < 4; mt++) {
#pragma unroll
        for (int nt = 0; nt < 4; nt++) {
            OutT* dst = C + (size_t)(m0 + wm * 64 + mt * 16 + gr) * ldc
                          + n0 + wn * 32 + nt * 8 + gc;
            if (sizeof(OutT) == 2) {
                *(uint32_t*)dst = pack_h(acc[mt][nt][0], acc[mt][nt][1]);
                *(uint32_t*)(dst + (size_t)8 * ldc) =
                    pack_h(acc[mt][nt][2], acc[mt][nt][3]);
            } else {
                *(float2*)dst = make_float2(acc[mt][nt][0], acc[mt][nt][1]);
                *(float2*)(dst + (size_t)8 * ldc) =
                    make_float2(acc[mt][nt][2], acc[mt][nt][3]);
            }
        }
    }
}

// ---------------- fused pos_unit helper (per 4 elems, 16-lane row groups) ---
__device__ __forceinline__ float4 posunit4(float4 v) {
    float4 p;
    p.x = v.x > 0.f ? v.x + 1.f : __expf(v.x);
    p.y = v.y > 0.f ? v.y + 1.f : __expf(v.y);
    p.z = v.z > 0.f ? v.z + 1.f : __expf(v.z);
    p.w = v.w > 0.f ? v.w + 1.f : __expf(v.w);
    float s = p.x * p.x + p.y * p.y + p.z * p.z + p.w * p.w;
    s += __shfl_xor_sync(0xffffffffu, s, 8);
    s += __shfl_xor_sync(0xffffffffu, s, 4);
    s += __shfl_xor_sync(0xffffffffu, s, 2);
    s += __shfl_xor_sync(0xffffffffu, s, 1);
    float inv = 1.0f / (sqrtf(s) + EPSF);
    p.x *= inv; p.y *= inv; p.z *= inv; p.w *= inv;
    return p;
}

// ---------------- per-chunk sums (scalar FFMA, 256 threads) -----------------
__global__ void __launch_bounds__(256) chunksum_kernel(
    const __half* __restrict__ qkv, float* __restrict__ Sc, float* __restrict__ kcs)
{
    __shared__ float ks[64 * 64];
    __shared__ float vs[64 * 64];
    const int tid = threadIdx.x;
    const int c = blockIdx.x, bh = blockIdx.y;
    const int b = bh >> 2, h = bh & 3;
    const int nbase = b * TT + c * CHUNK;
    const int rowb = tid >> 4;
    const int dq = (tid & 15) * 4;
#pragma unroll
    for (int rep = 0; rep < 4; rep++) {
        int t = rowb + rep * 16;
        const __half* src = qkv + (size_t)(nbase + t) * QKVW + h * 64 + dq;
        float4 k4 = posunit4(h4f(*(const uint2*)(src + 256)));
        *(float4*)&ks[t * 64 + dq] = k4;
        *(float4*)&vs[t * 64 + dq] = h4f(*(const uint2*)(src + 512));
    }
    __syncthreads();
    const int tx = tid & 15, ty = tid >> 4;
    float acc[4][4];
#pragma unroll
    for (int i = 0; i < 4; i++)
#pragma unroll
        for (int j = 0; j < 4; j++) acc[i][j] = 0.f;
    for (int t = 0; t < 64; t++) {
        float4 vv = *(const float4*)&vs[t * 64 + ty * 4];
        float4 kv = *(const float4*)&ks[t * 64 + tx * 4];
        float vm[4] = {vv.x, vv.y, vv.z, vv.w};
        float km[4] = {kv.x, kv.y, kv.z, kv.w};
#pragma unroll
        for (int i = 0; i < 4; i++)
#pragma unroll
            for (int j = 0; j < 4; j++)
                acc[i][j] += vm[i] * km[j];
    }
    size_t base = ((size_t)bh * NCH + c) * 4096;
#pragma unroll
    for (int i = 0; i < 4; i++) {
        float4 o = make_float4(acc[i][0], acc[i][1], acc[i][2], acc[i][3]);
        *(float4*)(Sc + base + (size_t)(ty * 4 + i) * 64 + tx * 4) = o;
    }
    if (tid < 64) {
        float s = 0.f;
        for (int t = 0; t < 64; t++) s += ks[t * 64 + tid];
        kcs[((size_t)bh * NCH + c) * 64 + tid] = s;
    }
}

// ---------------- exclusive prefix over chunks; S0 written as fp16 ---------
__global__ void __launch_bounds__(256) prefix_kernel(
    const float* __restrict__ Sc, const float* __restrict__ kcs,
    __half* __restrict__ S0, float* __restrict__ kc0,
    float* __restrict__ dout, int out_size)
{
    const int tid = threadIdx.x;
    const int bh = blockIdx.y;
    const int e = blockIdx.x * 256 + tid;   // 0..4095
    float acc = 0.f;
    size_t idx = (size_t)bh * NCH * 4096 + e;
#pragma unroll 4
    for (int c = 0; c < NCH; c += 4) {
        float v0 = Sc[idx];
        float v1 = Sc[idx + 4096];
        float v2 = Sc[idx + 8192];
        float v3 = Sc[idx + 12288];
        S0[idx] = __float2half_rn(acc);          acc += v0;
        S0[idx + 4096] = __float2half_rn(acc);   acc += v1;
        S0[idx + 8192] = __float2half_rn(acc);   acc += v2;
        S0[idx + 12288] = __float2half_rn(acc);  acc += v3;
        idx += 4 * 4096;
    }
    int kvoff = YSZ + bh * 4096 + e;
    if (kvoff < out_size) dout[kvoff] = acc;    // kv_f [B,H,j,d] (fp32, exact)
    if (blockIdx.x == 0 && tid < 64) {
        float a2 = 0.f;
        size_t kidx = (size_t)bh * NCH * 64 + tid;
#pragma unroll 4
        for (int c = 0; c < NCH; c += 4) {
            float v0 = kcs[kidx];
            float v1 = kcs[kidx + 64];
            float v2 = kcs[kidx + 128];
            float v3 = kcs[kidx + 192];
            kc0[kidx] = a2;        a2 += v0;
            kc0[kidx + 64] = a2;   a2 += v1;
            kc0[kidx + 128] = a2;  a2 += v2;
            kc0[kidx + 192] = a2;  a2 += v3;
            kidx += 256;
        }
        int kcoff = YSZ + KVSZ + bh * 64 + tid;
        if (kcoff < out_size) dout[kcoff] = a2; // kc_f [B,H,d]
    }
}

// =========== intra-chunk attention via split-fp16 HMMA ======================
// v, S0 are fp16-exact -> their lo terms vanish: 7 mm64 calls, 6 smem buffers.
#define IST 72
#define IBUF (64 * IST)
#define INTRA_SMEM (6 * IBUF * 2 + 128 * 4)   // 55808 B

// one 64x64x64 MMA-accumulate: acc += A(sA) @ B(sB)^T, warp tile 16x32
__device__ __forceinline__ void mm64(
    uint32_t sA, uint32_t sB, int wm, int wn, int lane, float acc[4][4])
{
    const uint32_t aBase = sA +
        (((uint32_t)(wm * 16 + (lane & 15)) * IST + ((lane >> 4) * 8)) * 2);
    const uint32_t bBase = sB +
        (((uint32_t)(wn * 32 + (lane & 7) + ((lane >> 4) << 3)) * IST + (lane & 8)) * 2);
#pragma unroll
    for (int ks = 0; ks < 4; ks++) {
        const uint32_t ko = ks * 32;   // 16 halves
        uint32_t af[4], bf0[4], bf1[4];
        LDMX4(af, aBase + ko);
        LDMX4(bf0, bBase + ko);
        LDMX4(bf1, bBase + ko + 16 * IST * 2);
        MMA_FP16(acc[0], af, &bf0[0]);
        MMA_FP16(acc[1], af, &bf0[2]);
        MMA_FP16(acc[2], af, &bf1[0]);
        MMA_FP16(acc[3], af, &bf1[2]);
    }
}

__global__ void __launch_bounds__(256) intra_kernel(
    const __half* __restrict__ qkv, const __half* __restrict__ S0g,
    const float* __restrict__ kc0g,
    __half* __restrict__ yh)
{
    extern __shared__ __align__(128) char ism[];
    __half* bufs = (__half*)ism;
    __half* Qh  = bufs;             __half* Ql  = bufs + 1 * IBUF;
    __half* Ahb = bufs + 2 * IBUF;  __half* Alb = bufs + 3 * IBUF;  // K then A
    __half* Vth = bufs + 4 * IBUF;
    __half* S0h = bufs + 5 * IBUF;
    float* dens = (float*)(bufs + 6 * IBUF);
    float* kc0s = dens + 64;

    const uint32_t sQh = smem_to_u32(Qh),  sQl = smem_to_u32(Ql);
    const uint32_t sAh = smem_to_u32(Ahb), sAl = smem_to_u32(Alb);
    const uint32_t sVh = smem_to_u32(Vth);
    const uint32_t sSh = smem_to_u32(S0h);

    const int tid = threadIdx.x;
    const int w = tid >> 5, lane = tid & 31;
    const int c = blockIdx.x, bh = blockIdx.y;
    const int b = bh >> 2, h = bh & 3;
    const int nbase = b * TT + c * CHUNK;
    const int rowb = tid >> 4;
    const int dq = (tid & 15) * 4;
    const size_t s0base = ((size_t)bh * NCH + c) * 4096;

    // ---- load + posunit + split to fp16 smem ----
#pragma unroll
    for (int rep = 0; rep < 4; rep++) {
        int t = rowb + rep * 16;
        const __half* src = qkv + (size_t)(nbase + t) * QKVW + h * 64 + dq;
        float4 q4 = posunit4(h4f(*(const uint2*)(src)));
        float4 k4 = posunit4(h4f(*(const uint2*)(src + 256)));
        uint2 v2 = *(const uint2*)(src + 512);               // fp16-exact
        uint2 s2 = *(const uint2*)(S0g + s0base + (size_t)t * 64 + dq); // fp16
        uint2 hh, ll;
        split4h(q4, hh, ll);
        *(uint2*)&Qh[t * IST + dq] = hh;  *(uint2*)&Ql[t * IST + dq] = ll;
        split4h(k4, hh, ll);
        *(uint2*)&Ahb[t * IST + dq] = hh; *(uint2*)&Alb[t * IST + dq] = ll;
        *(uint2*)&S0h[t * IST + dq] = s2;
        // V transposed: Vt[j][t]
        __half2 va = *(__half2*)&v2.x;
        __half2 vb = *(__half2*)&v2.y;
        Vth[(dq + 0) * IST + t] = va.x;
        Vth[(dq + 1) * IST + t] = va.y;
        Vth[(dq + 2) * IST + t] = vb.x;
        Vth[(dq + 3) * IST + t] = vb.y;
    }
    if (tid < 64) {
        dens[tid] = EPSF;
        kc0s[tid] = kc0g[((size_t)bh * NCH + c) * 64 + tid];
    }
    __syncthreads();

    const int wm = w >> 1, wn = w & 1;      // 4x2 warp grid, tile 16x32
    const int gr = lane >> 2, gc = (lane & 3) * 2;
    const int r0 = wm * 16 + gr, r1 = r0 + 8;

    // ---- A = Q K^T (3 split terms) ----
    float a4[4][4];
#pragma unroll
    for (int nt = 0; nt < 4; nt++)
#pragma unroll
        for (int r = 0; r < 4; r++) a4[nt][r] = 0.f;
    mm64(sQh, sAh, wm, wn, lane, a4);
    mm64(sQh, sAl, wm, wn, lane, a4);
    mm64(sQl, sAh, wm, wn, lane, a4);
    __syncthreads();   // everyone done reading K before A overwrites it

    // ---- mask tril, row-sums, split-store A over K buffers ----
    float s0 = 0.f, s1 = 0.f;
#pragma unroll
    for (int nt = 0; nt < 4; nt++) {
        int c0 = wn * 32 + nt * 8 + gc;
        float m00 = (c0     <= r0) ? a4[nt][0] : 0.f;
        float m01 = (c0 + 1 <= r0) ? a4[nt][1] : 0.f;
        float m10 = (c0     <= r1) ? a4[nt][2] : 0.f;
        float m11 = (c0 + 1 <= r1) ? a4[nt][3] : 0.f;
        s0 += m00 + m01;
        s1 += m10 + m11;
        uint32_t hh, ll;
        split2h(m00, m01, hh, ll);
        *(uint32_t*)&Ahb[r0 * IST + c0] = hh;
        *(uint32_t*)&Alb[r0 * IST + c0] = ll;
        split2h(m10, m11, hh, ll);
        *(uint32_t*)&Ahb[r1 * IST + c0] = hh;
        *(uint32_t*)&Alb[r1 * IST + c0] = ll;
    }
    s0 += __shfl_xor_sync(0xffffffffu, s0, 1);
    s0 += __shfl_xor_sync(0xffffffffu, s0, 2);
    s1 += __shfl_xor_sync(0xffffffffu, s1, 1);
    s1 += __shfl_xor_sync(0xffffffffu, s1, 2);
    if ((lane & 3) == 0) {
        atomicAdd(&dens[r0], s0);
        atomicAdd(&dens[r1], s1);
    }
    // den += q . kc0 (exact q = Qh + Ql)
    if (tid < 64) {
        float qd = 0.f;
        for (int dd = 0; dd < 64; dd++)
            qd += (__half2float(Qh[tid * IST + dd]) +
                   __half2float(Ql[tid * IST + dd])) * kc0s[dd];
        atomicAdd(&dens[tid], qd);
    }
    __syncthreads();

    // ---- num = A V + Q S0 (2 + 2 terms; Vl = S0l = 0) ----
    float y4[4][4];
#pragma unroll
    for (int nt = 0; nt < 4; nt++)
#pragma unroll
        for (int r = 0; r < 4; r++) y4[nt][r] = 0.f;
    mm64(sAh, sVh, wm, wn, lane, y4);
    mm64(sAl, sVh, wm, wn, lane, y4);
    mm64(sQh, sSh, wm, wn, lane, y4);
    mm64(sQl, sSh, wm, wn, lane, y4);

    const float inv0 = 1.0f / dens[r0];
    const float inv1 = 1.0f / dens[r1];
#pragma unroll
    for (int nt = 0; nt < 4; nt++) {
        int c0 = wn * 32 + nt * 8 + gc;
        size_t off0 = (size_t)(nbase + r0) * 256 + h * 64 + c0;
        *(uint32_t*)&yh[off0] = pack_h(y4[nt][0] * inv0, y4[nt][1] * inv0);
        size_t off1 = (size_t)(nbase + r1) * 256 + h * 64 + c0;
        *(uint32_t*)&yh[off1] = pack_h(y4[nt][2] * inv1, y4[nt][3] * inv1);
    }
}

// ---------------------------------------------------------------------------
extern "C" void kernel_launch(void* const* d_in, const int* in_sizes, int n_in,
                              void* d_out, int out_size)
{
    const float* x  = (const float*)d_in[0];
    const float* Wq = (const float*)d_in[1];
    const float* Wk = (const float*)d_in[2];
    const float* Wv = (const float*)d_in[3];
    const float* Wo = (const float*)d_in[4];
    float* out = (float*)d_out;

    float *Sc, *kc, *kc0;
    __half *qkv, *S0, *xh, *Wh, *Woh, *yh;
    cudaGetSymbolAddress((void**)&qkv, g_qkv);
    cudaGetSymbolAddress((void**)&Sc,  g_Sc);
    cudaGetSymbolAddress((void**)&S0,  g_S0);
    cudaGetSymbolAddress((void**)&kc,  g_kc);
    cudaGetSymbolAddress((void**)&kc0, g_kc0);
    cudaGetSymbolAddress((void**)&xh,  g_xh);
    cudaGetSymbolAddress((void**)&Wh,  g_Wh);
    cudaGetSymbolAddress((void**)&Woh, g_Woh);
    cudaGetSymbolAddress((void**)&yh,  g_yh);

    cudaFuncSetAttribute(intra_kernel,
                         cudaFuncAttributeMaxDynamicSharedMemorySize, INTRA_SMEM);
    cudaFuncSetAttribute(hmma_gemm_fp16<__half>,
                         cudaFuncAttributeMaxDynamicSharedMemorySize, GEMM_SMEM);
    cudaFuncSetAttribute(hmma_gemm_fp16<float>,
                         cudaFuncAttributeMaxDynamicSharedMemorySize, GEMM_SMEM);

    // operand preparation: x -> fp16 (rounded); weights -> fp16
    convert_round<<<(NTOK * DDIM / 4 + 255) / 256, 256>>>(
        (const float4*)x, (uint2*)xh, NTOK * DDIM / 4);
    convert_weights<<<dim3(256, 4), 256>>>(
        (const float4*)Wq, (const float4*)Wk, (const float4*)Wv,
        (const float4*)Wo, (uint2*)Wh, (uint2*)Woh);

    // QKV projection: qkv[t][0:768] = xh @ [Wq;Wk;Wv]^T  (fp16 output)
    hmma_gemm_fp16<__half><<<dim3(6, NTOK / 128), 256, GEMM_SMEM>>>(
        xh, DDIM, Wh, DDIM, qkv, QKVW, DDIM);

    // chunked linear-attention scan (posunit fused into consumers)
    chunksum_kernel<<<dim3(NCH, NBH), 256>>>(qkv, Sc, kc);
    prefix_kernel<<<dim3(16, NBH), 256>>>(Sc, kc, S0, kc0, out, out_size);
    intra_kernel<<<dim3(NCH, NBH), 256, INTRA_SMEM>>>(qkv, S0, kc0, yh);

    // output projection: out = yh @ Wo^T (fp32 output)
    hmma_gemm_fp16<float><<<dim3(8, NTOK / 128), 256, GEMM_SMEM>>>(
        yh, 256, Woh, 256, out, DDIM, 256);
}

// round 16
// speedup vs baseline: 1.4286x; 1.0090x over previous
#include <cuda_runtime.h>
#include <cuda_fp16.h>
#include <cstdint>

#define EPSF 1e-6f

// Problem constants (B=4, T=4096, D=1024, H=4, d=64)
#define BB    4
#define TT    4096
#define DDIM  1024
#define HH    4
#define HD    64
#define NTOK  (BB*TT)        // 16384
#define QKVW  768
#define CHUNK 64
#define NCH   (TT/CHUNK)     // 64
#define NBH   (BB*HH)        // 16
#define YSZ   (16777216)     // NTOK*DDIM
#define KVSZ  (65536)        // NBH*64*64

// ---------------- scratch (device globals; no allocations allowed) ----------
__device__ __align__(128) __half g_qkv[(size_t)NTOK * QKVW];         // 24 MB (fp16)
__device__ __align__(128) float g_Sc [(size_t)NBH * NCH * 4096];     // 16 MB
__device__ __align__(128) __half g_S0[(size_t)NBH * NCH * 4096];     // 8 MB (fp16)
__device__ __align__(128) float g_kc [(size_t)NBH * NCH * 64];
__device__ __align__(128) float g_kc0[(size_t)NBH * NCH * 64];
// fp16 operand copies
__device__ __align__(128) __half g_xh[(size_t)NTOK * DDIM];          // 32 MB
__device__ __align__(128) __half g_Wh[(size_t)QKVW * DDIM];          // 1.5 MB
__device__ __align__(128) __half g_Woh[(size_t)DDIM * 256];
__device__ __align__(128) __half g_yh[(size_t)NTOK * 256];           // 8 MB

// ======================= PTX helpers (arch-neutral) =========================
__device__ __forceinline__ uint32_t smem_to_u32(const void* p) {
    uint32_t a;
    asm("{ .reg .u64 t; cvta.to.shared.u64 t, %1; cvt.u32.u64 %0, t; }"
        : "=r"(a) : "l"(p));
    return a;
}
#define LDMX4(R, addr) \
    asm volatile("ldmatrix.sync.aligned.m8n8.x4.shared.b16 {%0,%1,%2,%3}, [%4];" \
        : "=r"((R)[0]), "=r"((R)[1]), "=r"((R)[2]), "=r"((R)[3]) : "r"(addr))
#define MMA_FP16(D, A, B) \
    asm volatile("mma.sync.aligned.m16n8k16.row.col.f32.f16.f16.f32 " \
        "{%0,%1,%2,%3},{%4,%5,%6,%7},{%8,%9},{%0,%1,%2,%3};" \
        : "+f"((D)[0]), "+f"((D)[1]), "+f"((D)[2]), "+f"((D)[3]) \
        : "r"((A)[0]), "r"((A)[1]), "r"((A)[2]), "r"((A)[3]), \
          "r"((B)[0]), "r"((B)[1]))
__device__ __forceinline__ void cpa16(uint32_t dst, const void* src) {
    asm volatile("cp.async.cg.shared.global [%0], [%1], 16;"
                 :: "r"(dst), "l"(src) : "memory");
}
#define CPA_COMMIT() asm volatile("cp.async.commit_group;" ::: "memory")
#define CPA_WAIT1()  asm volatile("cp.async.wait_group 1;"  ::: "memory")

__device__ __forceinline__ uint32_t pack_h(float a, float b) {
    __half2 t;
    t.x = __float2half_rn(a);
    t.y = __float2half_rn(b);
    return *(uint32_t*)&t;
}
// exact fp16 (hi, lo) split of a float pair
__device__ __forceinline__ void split2h(float a, float b, uint32_t& h, uint32_t& l) {
    float ha = __half2float(__float2half_rn(a));
    float hb = __half2float(__float2half_rn(b));
    h = pack_h(a, b);
    l = pack_h(a - ha, b - hb);
}
// exact fp16 (hi, lo) split of a float4
__device__ __forceinline__ void split4h(float4 v, uint2& h, uint2& l) {
    split2h(v.x, v.y, h.x, l.x);
    split2h(v.z, v.w, h.y, l.y);
}
// 4 halves (uint2) -> float4
__device__ __forceinline__ float4 h4f(uint2 u) {
    __half2 a = *(__half2*)&u.x;
    __half2 b = *(__half2*)&u.y;
    return make_float4(__half2float(a.x), __half2float(a.y),
                       __half2float(b.x), __half2float(b.y));
}

// ---------------- one launch: x -> fp16 and all 4 weights -> fp16 -----------
#define NX4 (NTOK * DDIM / 4)        // 4194304 float4 in x
__global__ void __launch_bounds__(256) convert_all(
    const float4* __restrict__ x,
    const float4* __restrict__ Wq, const float4* __restrict__ Wk,
    const float4* __restrict__ Wv, const float4* __restrict__ Wo,
    uint2* __restrict__ xh, uint2* __restrict__ Wh, uint2* __restrict__ Woh)
{
    const int i = blockIdx.x * 256 + threadIdx.x;
    if (i < NX4) {
        float4 v = x[i];
        xh[i] = make_uint2(pack_h(v.x, v.y), pack_h(v.z, v.w));
    } else {
        int j = i - NX4;                 // 0..262143
        int m = j >> 16, jj = j & 65535;
        const float4* src = (m == 0) ? Wq : (m == 1) ? Wk : (m == 2) ? Wv : Wo;
        float4 v = src[jj];
        uint2 r = make_uint2(pack_h(v.x, v.y), pack_h(v.z, v.w));
        if (m < 3) Wh[(size_t)m * 65536 + jj] = r;
        else       Woh[jj] = r;
    }
}

// ====== fp16 HMMA GEMM: C = Ah @ Bh^T (BK=32, 3-stage) ======================
#define LDS_A   40
#define TILE_B  (128 * LDS_A * 2)
#define NSTAGE  3
#define GEMM_SMEM (NSTAGE * 2 * TILE_B)   // 61440

template <typename OutT>
__global__ void __launch_bounds__(256, 2) hmma_gemm_fp16(
    const __half* __restrict__ Ah, int lda,
    const __half* __restrict__ Bh, int ldb,
    OutT* __restrict__ C, int ldc, int K)
{
    extern __shared__ __align__(128) char smem[];
    const uint32_t sbase = smem_to_u32(smem);
    const int tid = threadIdx.x;
    const int w = tid >> 5, lane = tid & 31;
    const int m0 = blockIdx.y * 128;
    const int n0 = blockIdx.x * 128;

    const int row0 = tid >> 2, c16 = tid & 3;
    const int row1 = (tid + 256) >> 2;
    const uint32_t d0 = (uint32_t)row0 * (LDS_A * 2) + c16 * 16;
    const uint32_t d1 = (uint32_t)row1 * (LDS_A * 2) + c16 * 16;
    const size_t aoff0 = (size_t)(m0 + row0) * lda + c16 * 8;
    const size_t aoff1 = (size_t)(m0 + row1) * lda + c16 * 8;
    const size_t boff0 = (size_t)(n0 + row0) * ldb + c16 * 8;
    const size_t boff1 = (size_t)(n0 + row1) * ldb + c16 * 8;

#define ISSUE_STAGE(sb, koff) do { \
        cpa16((sb) + d0, Ah + aoff0 + (koff)); \
        cpa16((sb) + d1, Ah + aoff1 + (koff)); \
        cpa16((sb) + TILE_B + d0, Bh + boff0 + (koff)); \
        cpa16((sb) + TILE_B + d1, Bh + boff1 + (koff)); \
    } while (0)

    float acc[4][4][4];
#pragma unroll
    for (int mt = 0; mt < 4; mt++)
#pragma unroll
        for (int nt = 0; nt < 4; nt++)
#pragma unroll
            for (int r = 0; r < 4; r++) acc[mt][nt][r] = 0.f;

    const int wm = w >> 2, wn = w & 3;
    const int aRow = wm * 64 + (lane & 15);
    const int aCol = (lane >> 4) * 8;
    const int bRow = wn * 32 + (lane & 7) + ((lane >> 4) << 3);
    const int bCol = (lane & 8);

    const int NC = K / 32;

    ISSUE_STAGE(sbase, 0);
    CPA_COMMIT();
    ISSUE_STAGE(sbase + 2 * TILE_B, 32);
    CPA_COMMIT();

    int s = 0;
    for (int c = 0; c < NC; c++) {
        CPA_WAIT1();
        __syncthreads();
        if (c + 2 < NC) {
            int s2 = s + 2; if (s2 >= NSTAGE) s2 -= NSTAGE;
            ISSUE_STAGE(sbase + s2 * (2 * TILE_B), (c + 2) * 32);
        }
        CPA_COMMIT();

        const uint32_t st = sbase + s * (2 * TILE_B);
        const uint32_t sA = st, sB = st + TILE_B;
#pragma unroll
        for (int ks = 0; ks < 2; ks++) {
            const int kb = ks * 16;
            uint32_t bAddr = ((uint32_t)bRow * LDS_A + kb + bCol) * 2;
            uint32_t aAddr = ((uint32_t)aRow * LDS_A + kb + aCol) * 2;
            uint32_t bf[2][4], af[4][4];
#pragma unroll
            for (int nt2 = 0; nt2 < 2; nt2++)
                LDMX4(bf[nt2], sB + bAddr + nt2 * (16 * LDS_A * 2));
#pragma unroll
            for (int mt = 0; mt < 4; mt++)
                LDMX4(af[mt], sA + aAddr + mt * (16 * LDS_A * 2));
#pragma unroll
            for (int mt = 0; mt < 4; mt++)
#pragma unroll
                for (int nt = 0; nt < 4; nt++)
                    MMA_FP16(acc[mt][nt], af[mt], &bf[nt >> 1][(nt & 1) * 2]);
        }
        if (++s == NSTAGE) s = 0;
    }
#undef ISSUE_STAGE

    const int gr = lane >> 2, gc = (lane & 3) * 2;
#pragma unroll
    for (int mt = 0; mt < 4; mt++) {
#pragma unroll
        for (int nt = 0; nt < 4; nt++) {
            OutT* dst = C + (size_t)(m0 + wm * 64 + mt * 16 + gr) * ldc
                          + n0 + wn * 32 + nt * 8 + gc;
            if (sizeof(OutT) == 2) {
                *(uint32_t*)dst = pack_h(acc[mt][nt][0], acc[mt][nt][1]);
                *(uint32_t*)(dst + (size_t)8 * ldc) =
                    pack_h(acc[mt][nt][2], acc[mt][nt][3]);
            } else {
                *(float2*)dst = make_float2(acc[mt][nt][0], acc[mt][nt][1]);
                *(float2*)(dst + (size_t)8 * ldc) =
                    make_float2(acc[mt][nt][2], acc[mt][nt][3]);
            }
        }
    }
}

// ---------------- fused pos_unit helper (per 4 elems, 16-lane row groups) ---
__device__ __forceinline__ float4 posunit4(float4 v) {
    float4 p;
    p.x = v.x > 0.f ? v.x + 1.f : __expf(v.x);
    p.y = v.y > 0.f ? v.y + 1.f : __expf(v.y);
    p.z = v.z > 0.f ? v.z + 1.f : __expf(v.z);
    p.w = v.w > 0.f ? v.w + 1.f : __expf(v.w);
    float s = p.x * p.x + p.y * p.y + p.z * p.z + p.w * p.w;
    s += __shfl_xor_sync(0xffffffffu, s, 8);
    s += __shfl_xor_sync(0xffffffffu, s, 4);
    s += __shfl_xor_sync(0xffffffffu, s, 2);
    s += __shfl_xor_sync(0xffffffffu, s, 1);
    float inv = 1.0f / (sqrtf(s) + EPSF);
    p.x *= inv; p.y *= inv; p.z *= inv; p.w *= inv;
    return p;
}

// ---------------- per-chunk sums (scalar FFMA, 256 threads) -----------------
__global__ void __launch_bounds__(256) chunksum_kernel(
    const __half* __restrict__ qkv, float* __restrict__ Sc, float* __restrict__ kcs)
{
    __shared__ float ks[64 * 64];
    __shared__ float vs[64 * 64];
    const int tid = threadIdx.x;
    const int c = blockIdx.x, bh = blockIdx.y;
    const int b = bh >> 2, h = bh & 3;
    const int nbase = b * TT + c * CHUNK;
    const int rowb = tid >> 4;
    const int dq = (tid & 15) * 4;
#pragma unroll
    for (int rep = 0; rep < 4; rep++) {
        int t = rowb + rep * 16;
        const __half* src = qkv + (size_t)(nbase + t) * QKVW + h * 64 + dq;
        float4 k4 = posunit4(h4f(*(const uint2*)(src + 256)));
        *(float4*)&ks[t * 64 + dq] = k4;
        *(float4*)&vs[t * 64 + dq] = h4f(*(const uint2*)(src + 512));
    }
    __syncthreads();
    const int tx = tid & 15, ty = tid >> 4;
    float acc[4][4];
#pragma unroll
    for (int i = 0; i < 4; i++)
#pragma unroll
        for (int j = 0; j < 4; j++) acc[i][j] = 0.f;
    for (int t = 0; t < 64; t++) {
        float4 vv = *(const float4*)&vs[t * 64 + ty * 4];
        float4 kv = *(const float4*)&ks[t * 64 + tx * 4];
        float vm[4] = {vv.x, vv.y, vv.z, vv.w};
        float km[4] = {kv.x, kv.y, kv.z, kv.w};
#pragma unroll
        for (int i = 0; i < 4; i++)
#pragma unroll
            for (int j = 0; j < 4; j++)
                acc[i][j] += vm[i] * km[j];
    }
    size_t base = ((size_t)bh * NCH + c) * 4096;
#pragma unroll
    for (int i = 0; i < 4; i++) {
        float4 o = make_float4(acc[i][0], acc[i][1], acc[i][2], acc[i][3]);
        *(float4*)(Sc + base + (size_t)(ty * 4 + i) * 64 + tx * 4) = o;
    }
    if (tid < 64) {
        float s = 0.f;
        for (int t = 0; t < 64; t++) s += ks[t * 64 + tid];
        kcs[((size_t)bh * NCH + c) * 64 + tid] = s;
    }
}

// ---------------- exclusive prefix over chunks; S0 written as fp16 ---------
__global__ void __launch_bounds__(256) prefix_kernel(
    const float* __restrict__ Sc, const float* __restrict__ kcs,
    __half* __restrict__ S0, float* __restrict__ kc0,
    float* __restrict__ dout, int out_size)
{
    const int tid = threadIdx.x;
    const int bh = blockIdx.y;
    const int e = blockIdx.x * 256 + tid;   // 0..4095
    float acc = 0.f;
    size_t idx = (size_t)bh * NCH * 4096 + e;
#pragma unroll 4
    for (int c = 0; c < NCH; c += 4) {
        float v0 = Sc[idx];
        float v1 = Sc[idx + 4096];
        float v2 = Sc[idx + 8192];
        float v3 = Sc[idx + 12288];
        S0[idx] = __float2half_rn(acc);          acc += v0;
        S0[idx + 4096] = __float2half_rn(acc);   acc += v1;
        S0[idx + 8192] = __float2half_rn(acc);   acc += v2;
        S0[idx + 12288] = __float2half_rn(acc);  acc += v3;
        idx += 4 * 4096;
    }
    int kvoff = YSZ + bh * 4096 + e;
    if (kvoff < out_size) dout[kvoff] = acc;    // kv_f [B,H,j,d] (fp32, exact)
    if (blockIdx.x == 0 && tid < 64) {
        float a2 = 0.f;
        size_t kidx = (size_t)bh * NCH * 64 + tid;
#pragma unroll 4
        for (int c = 0; c < NCH; c += 4) {
            float v0 = kcs[kidx];
            float v1 = kcs[kidx + 64];
            float v2 = kcs[kidx + 128];
            float v3 = kcs[kidx + 192];
            kc0[kidx] = a2;        a2 += v0;
            kc0[kidx + 64] = a2;   a2 += v1;
            kc0[kidx + 128] = a2;  a2 += v2;
            kc0[kidx + 192] = a2;  a2 += v3;
            kidx += 256;
        }
        int kcoff = YSZ + KVSZ + bh * 64 + tid;
        if (kcoff < out_size) dout[kcoff] = a2; // kc_f [B,H,d]
    }
}

// =========== intra-chunk attention via split-fp16 HMMA ======================
// v, S0 are fp16-exact -> their lo terms vanish: 7 mm64 calls, 6 smem buffers.
#define IST 72
#define IBUF (64 * IST)
#define INTRA_SMEM (6 * IBUF * 2 + 128 * 4)   // 55808 B

// one 64x64x64 MMA-accumulate: acc += A(sA) @ B(sB)^T, warp tile 16x32
__device__ __forceinline__ void mm64(
    uint32_t sA, uint32_t sB, int wm, int wn, int lane, float acc[4][4])
{
    const uint32_t aBase = sA +
        (((uint32_t)(wm * 16 + (lane & 15)) * IST + ((lane >> 4) * 8)) * 2);
    const uint32_t bBase = sB +
        (((uint32_t)(wn * 32 + (lane & 7) + ((lane >> 4) << 3)) * IST + (lane & 8)) * 2);
#pragma unroll
    for (int ks = 0; ks < 4; ks++) {
        const uint32_t ko = ks * 32;   // 16 halves
        uint32_t af[4], bf0[4], bf1[4];
        LDMX4(af, aBase + ko);
        LDMX4(bf0, bBase + ko);
        LDMX4(bf1, bBase + ko + 16 * IST * 2);
        MMA_FP16(acc[0], af, &bf0[0]);
        MMA_FP16(acc[1], af, &bf0[2]);
        MMA_FP16(acc[2], af, &bf1[0]);
        MMA_FP16(acc[3], af, &bf1[2]);
    }
}

__global__ void __launch_bounds__(256) intra_kernel(
    const __half* __restrict__ qkv, const __half* __restrict__ S0g,
    const float* __restrict__ kc0g,
    __half* __restrict__ yh)
{
    extern __shared__ __align__(128) char ism[];
    __half* bufs = (__half*)ism;
    __half* Qh  = bufs;             __half* Ql  = bufs + 1 * IBUF;
    __half* Ahb = bufs + 2 * IBUF;  __half* Alb = bufs + 3 * IBUF;  // K then A
    __half* Vth = bufs + 4 * IBUF;
    __half* S0h = bufs + 5 * IBUF;
    float* dens = (float*)(bufs + 6 * IBUF);
    float* kc0s = dens + 64;

    const uint32_t sQh = smem_to_u32(Qh),  sQl = smem_to_u32(Ql);
    const uint32_t sAh = smem_to_u32(Ahb), sAl = smem_to_u32(Alb);
    const uint32_t sVh = smem_to_u32(Vth);
    const uint32_t sSh = smem_to_u32(S0h);

    const int tid = threadIdx.x;
    const int w = tid >> 5, lane = tid & 31;
    const int c = blockIdx.x, bh = blockIdx.y;
    const int b = bh >> 2, h = bh & 3;
    const int nbase = b * TT + c * CHUNK;
    const int rowb = tid >> 4;
    const int dq = (tid & 15) * 4;
    const size_t s0base = ((size_t)bh * NCH + c) * 4096;

    // ---- load + posunit + split to fp16 smem ----
#pragma unroll
    for (int rep = 0; rep < 4; rep++) {
        int t = rowb + rep * 16;
        const __half* src = qkv + (size_t)(nbase + t) * QKVW + h * 64 + dq;
        float4 q4 = posunit4(h4f(*(const uint2*)(src)));
        float4 k4 = posunit4(h4f(*(const uint2*)(src + 256)));
        uint2 v2 = *(const uint2*)(src + 512);               // fp16-exact
        uint2 s2 = *(const uint2*)(S0g + s0base + (size_t)t * 64 + dq); // fp16
        uint2 hh, ll;
        split4h(q4, hh, ll);
        *(uint2*)&Qh[t * IST + dq] = hh;  *(uint2*)&Ql[t * IST + dq] = ll;
        split4h(k4, hh, ll);
        *(uint2*)&Ahb[t * IST + dq] = hh; *(uint2*)&Alb[t * IST + dq] = ll;
        *(uint2*)&S0h[t * IST + dq] = s2;
        // V transposed: Vt[j][t]
        __half2 va = *(__half2*)&v2.x;
        __half2 vb = *(__half2*)&v2.y;
        Vth[(dq + 0) * IST + t] = va.x;
        Vth[(dq + 1) * IST + t] = va.y;
        Vth[(dq + 2) * IST + t] = vb.x;
        Vth[(dq + 3) * IST + t] = vb.y;
    }
    if (tid < 64) {
        dens[tid] = EPSF;
        kc0s[tid] = kc0g[((size_t)bh * NCH + c) * 64 + tid];
    }
    __syncthreads();

    const int wm = w >> 1, wn = w & 1;      // 4x2 warp grid, tile 16x32
    const int gr = lane >> 2, gc = (lane & 3) * 2;
    const int r0 = wm * 16 + gr, r1 = r0 + 8;

    // ---- A = Q K^T (3 split terms) ----
    float a4[4][4];
#pragma unroll
    for (int nt = 0; nt < 4; nt++)
#pragma unroll
        for (int r = 0; r < 4; r++) a4[nt][r] = 0.f;
    mm64(sQh, sAh, wm, wn, lane, a4);
    mm64(sQh, sAl, wm, wn, lane, a4);
    mm64(sQl, sAh, wm, wn, lane, a4);
    __syncthreads();   // everyone done reading K before A overwrites it

    // ---- mask tril, row-sums, split-store A over K buffers ----
    float s0 = 0.f, s1 = 0.f;
#pragma unroll
    for (int nt = 0; nt < 4; nt++) {
        int c0 = wn * 32 + nt * 8 + gc;
        float m00 = (c0     <= r0) ? a4[nt][0] : 0.f;
        float m01 = (c0 + 1 <= r0) ? a4[nt][1] : 0.f;
        float m10 = (c0     <= r1) ? a4[nt][2] : 0.f;
        float m11 = (c0 + 1 <= r1) ? a4[nt][3] : 0.f;
        s0 += m00 + m01;
        s1 += m10 + m11;
        uint32_t hh, ll;
        split2h(m00, m01, hh, ll);
        *(uint32_t*)&Ahb[r0 * IST + c0] = hh;
        *(uint32_t*)&Alb[r0 * IST + c0] = ll;
        split2h(m10, m11, hh, ll);
        *(uint32_t*)&Ahb[r1 * IST + c0] = hh;
        *(uint32_t*)&Alb[r1 * IST + c0] = ll;
    }
    s0 += __shfl_xor_sync(0xffffffffu, s0, 1);
    s0 += __shfl_xor_sync(0xffffffffu, s0, 2);
    s1 += __shfl_xor_sync(0xffffffffu, s1, 1);
    s1 += __shfl_xor_sync(0xffffffffu, s1, 2);
    if ((lane & 3) == 0) {
        atomicAdd(&dens[r0], s0);
        atomicAdd(&dens[r1], s1);
    }
    // den += q . kc0 (exact q = Qh + Ql); all 256 threads, 4-way dd split
    {
        const int row = tid & 63, qtr = tid >> 6;
        const int d0 = qtr * 16;
        float qd = 0.f;
#pragma unroll
        for (int dd = d0; dd < d0 + 16; dd++)
            qd += (__half2float(Qh[row * IST + dd]) +
                   __half2float(Ql[row * IST + dd])) * kc0s[dd];
        atomicAdd(&dens[row], qd);
    }
    __syncthreads();

    // ---- num = A V + Q S0 (2 + 2 terms; Vl = S0l = 0) ----
    float y4[4][4];
#pragma unroll
    for (int nt = 0; nt < 4; nt++)
#pragma unroll
        for (int r = 0; r < 4; r++) y4[nt][r] = 0.f;
    mm64(sAh, sVh, wm, wn, lane, y4);
    mm64(sAl, sVh, wm, wn, lane, y4);
    mm64(sQh, sSh, wm, wn, lane, y4);
    mm64(sQl, sSh, wm, wn, lane, y4);

    const float inv0 = 1.0f / dens[r0];
    const float inv1 = 1.0f / dens[r1];
#pragma unroll
    for (int nt = 0; nt < 4; nt++) {
        int c0 = wn * 32 + nt * 8 + gc;
        size_t off0 = (size_t)(nbase + r0) * 256 + h * 64 + c0;
        *(uint32_t*)&yh[off0] = pack_h(y4[nt][0] * inv0, y4[nt][1] * inv0);
        size_t off1 = (size_t)(nbase + r1) * 256 + h * 64 + c0;
        *(uint32_t*)&yh[off1] = pack_h(y4[nt][2] * inv1, y4[nt][3] * inv1);
    }
}

// ---------------------------------------------------------------------------
extern "C" void kernel_launch(void* const* d_in, const int* in_sizes, int n_in,
                              void* d_out, int out_size)
{
    const float* x  = (const float*)d_in[0];
    const float* Wq = (const float*)d_in[1];
    const float* Wk = (const float*)d_in[2];
    const float* Wv = (const float*)d_in[3];
    const float* Wo = (const float*)d_in[4];
    float* out = (float*)d_out;

    float *Sc, *kc, *kc0;
    __half *qkv, *S0, *xh, *Wh, *Woh, *yh;
    cudaGetSymbolAddress((void**)&qkv, g_qkv);
    cudaGetSymbolAddress((void**)&Sc,  g_Sc);
    cudaGetSymbolAddress((void**)&S0,  g_S0);
    cudaGetSymbolAddress((void**)&kc,  g_kc);
    cudaGetSymbolAddress((void**)&kc0, g_kc0);
    cudaGetSymbolAddress((void**)&xh,  g_xh);
    cudaGetSymbolAddress((void**)&Wh,  g_Wh);
    cudaGetSymbolAddress((void**)&Woh, g_Woh);
    cudaGetSymbolAddress((void**)&yh,  g_yh);

    cudaFuncSetAttribute(intra_kernel,
                         cudaFuncAttributeMaxDynamicSharedMemorySize, INTRA_SMEM);
    cudaFuncSetAttribute(hmma_gemm_fp16<__half>,
                         cudaFuncAttributeMaxDynamicSharedMemorySize, GEMM_SMEM);
    cudaFuncSetAttribute(hmma_gemm_fp16<float>,
                         cudaFuncAttributeMaxDynamicSharedMemorySize, GEMM_SMEM);

    // operand preparation (single launch: x + all 4 weights)
    convert_all<<<(NX4 + 262144 + 255) / 256, 256>>>(
        (const float4*)x, (const float4*)Wq, (const float4*)Wk,
        (const float4*)Wv, (const float4*)Wo,
        (uint2*)xh, (uint2*)Wh, (uint2*)Woh);

    // QKV projection: qkv[t][0:768] = xh @ [Wq;Wk;Wv]^T  (fp16 output)
    hmma_gemm_fp16<__half><<<dim3(6, NTOK / 128), 256, GEMM_SMEM>>>(
        xh, DDIM, Wh, DDIM, qkv, QKVW, DDIM);

    // chunked linear-attention scan (posunit fused into consumers)
    chunksum_kernel<<<dim3(NCH, NBH), 256>>>(qkv, Sc, kc);
    prefix_kernel<<<dim3(16, NBH), 256>>>(Sc, kc, S0, kc0, out, out_size);
    intra_kernel<<<dim3(NCH, NBH), 256, INTRA_SMEM>>>(qkv, S0, kc0, yh);

    // output projection: out = yh @ Wo^T (fp32 output)
    hmma_gemm_fp16<float><<<dim3(8, NTOK / 128), 256, GEMM_SMEM>>>(
        yh, 256, Woh, 256, out, DDIM, 256);
}